// round 5
// baseline (speedup 1.0000x reference)
#include <cuda_runtime.h>
#include <cuda_fp16.h>
#include <math.h>
#include <stdint.h>

// Shapes (fixed)
#define HW_DIM  1024
#define C_DIM   256
#define N_TOK   32768
#define K_CODES 1024
#define Z_ELEMS 8388608
#define BETA_F  0.25f

// tiling
#define MT      128            // tokens per CTA
#define NCH     32             // codes per chunk (double-buffered)
#define CHUNKS  (K_CODES / NCH)   // 32
#define KSTEPS  (C_DIM / 16)      // 16

// fp16 split scale
#define LO_S    2048.0f
#define LO_IS   4.8828125e-4f

// padded row: 264 halves = 528 bytes (ldsm conflict-free: 528 % 128 = 16)
#define ROWH    264
#define ROWB    528

// smem layout (bytes)
#define AH_OFF  0
#define AL_OFF  67584                 // 128*528
#define B0_OFF  135168                // buf = BH(32*528) + BL(32*528) = 33792
#define B1_OFF  168960
#define BBUF    33792
#define BHALF   16896                 // 32*528
#define NS_OFF  202752                // 1024 floats
#define CV_OFF  206848                // 128*2 floats
#define CI_OFF  207872                // 128*2 ints
#define SMEM_TOTAL 208896

#define GL_BLOCKS 1024

static __device__ int    g_idx[N_TOK];
static __device__ int    g_counts[K_CODES];
static __device__ float  g_norms[K_CODES];
static __device__ float  g_partials[GL_BLOCKS];
static __device__ __half g_cbh[K_CODES * ROWH];
static __device__ __half g_cbl[K_CODES * ROWH];

// ---------------------------------------------------------------------------
__global__ void init_kernel() { g_counts[threadIdx.x] = 0; }

__device__ __forceinline__ void split16(float a, __half& hi, __half& lo) {
    hi = __float2half_rn(a);
    lo = __float2half_rn((a - __half2float(hi)) * LO_S);
}

// one-shot: split codebook into padded half hi/lo arrays
__global__ void split_cb_kernel(const float* __restrict__ cb) {
    int code = blockIdx.x;
    int c    = threadIdx.x;
    float v = cb[code * C_DIM + c];
    __half hi, lo;
    split16(v, hi, lo);
    g_cbh[code * ROWH + c] = hi;
    g_cbl[code * ROWH + c] = lo;
    if (c < ROWH - C_DIM) {                 // zero the pad
        g_cbh[code * ROWH + C_DIM + c] = __half(0.f);
        g_cbl[code * ROWH + C_DIM + c] = __half(0.f);
    }
}

__global__ void norms_kernel(const float* __restrict__ cb) {
    int code = blockIdx.x * 8 + (threadIdx.x >> 5);
    int lane = threadIdx.x & 31;
    const float* row = cb + code * C_DIM;
    float s = 0.f;
    #pragma unroll
    for (int c = lane; c < C_DIM; c += 32) { float v = row[c]; s += v * v; }
    #pragma unroll
    for (int off = 16; off > 0; off >>= 1)
        s += __shfl_down_sync(0xffffffffu, s, off);
    if (lane == 0) g_norms[code] = s;
}

// ---------------------------------------------------------------------------
__device__ __forceinline__ uint32_t smem_u32(const void* p) {
    uint32_t a;
    asm("{ .reg .u64 T; cvta.to.shared.u64 T, %1; cvt.u32.u64 %0, T; }"
        : "=r"(a) : "l"(p));
    return a;
}
__device__ __forceinline__ void ldsm4(uint32_t addr, uint32_t r[4]) {
    asm volatile("ldmatrix.sync.aligned.m8n8.x4.shared.b16 {%0,%1,%2,%3}, [%4];"
                 : "=r"(r[0]), "=r"(r[1]), "=r"(r[2]), "=r"(r[3]) : "r"(addr));
}
__device__ __forceinline__ void mma_f16(float c[4], const uint32_t a[4],
                                        uint32_t b0, uint32_t b1) {
    asm volatile(
        "mma.sync.aligned.m16n8k16.row.col.f32.f16.f16.f32 "
        "{%0,%1,%2,%3}, {%4,%5,%6,%7}, {%8,%9}, {%0,%1,%2,%3};"
        : "+f"(c[0]), "+f"(c[1]), "+f"(c[2]), "+f"(c[3])
        : "r"(a[0]), "r"(a[1]), "r"(a[2]), "r"(a[3]), "r"(b0), "r"(b1));
}
#define CP_ASYNC16(dst, src) \
    asm volatile("cp.async.cg.shared.global [%0], [%1], 16;" :: "r"(dst), "l"(src))
#define CP_COMMIT() asm volatile("cp.async.commit_group;" ::: "memory")
#define CP_WAIT1()  asm volatile("cp.async.wait_group 1;" ::: "memory")
#define CP_WAIT0()  asm volatile("cp.async.wait_group 0;" ::: "memory")

// ---------------------------------------------------------------------------
// split-fp16 tensor-core GEMM-argmin with cp.async double-buffered B.
// CTA: 128 tokens x 1024 codes (32 chunks of 32 codes).
// 8 warps = 4 token-groups x 2 code-groups; warp tile = 32 tok x 16 codes.
__global__ __launch_bounds__(256, 1)
void argmin_kernel(const float* __restrict__ z, const float* __restrict__ cb) {
    extern __shared__ char smem[];
    const uint32_t sb = smem_u32(smem);
    float* ns    = (float*)(smem + NS_OFF);
    float* candv = (float*)(smem + CV_OFF);
    int*   candi = (int*)(smem + CI_OFF);

    const int tid  = threadIdx.x;
    const int warp = tid >> 5;
    const int lane = tid & 31;
    const int tg   = warp & 3;     // token group (32 tokens)
    const int cg   = warp >> 2;    // code half of chunk (16 codes)
    const int g    = lane >> 2;
    const int t    = lane & 3;
    const int l15  = lane & 15;

    const int n0  = blockIdx.x * MT;
    const int b   = n0 >> 10;
    const int hw0 = n0 & 1023;
    const float* zb = z + (size_t)b * (C_DIM * HW_DIM) + hw0;

    // ---- prefetch B chunks 0 and 1 (hi+lo) via cp.async -------------------
    // per chunk: 32 rows x 33 x 16B per array; 2112 copies over 256 threads
    auto prefetch = [&](int ch, uint32_t bufoff) {
        const __half* srcH = g_cbh + (size_t)(ch * NCH) * ROWH;
        const __half* srcL = g_cbl + (size_t)(ch * NCH) * ROWH;
        #pragma unroll
        for (int it = 0; it < 9; it++) {
            int i = it * 256 + tid;
            if (i < 2112) {
                int arr = i >= 1056;
                int idx = arr ? i - 1056 : i;
                int row = idx / 33;
                int seg = idx - row * 33;
                const __half* src = (arr ? srcL : srcH) + row * ROWH + seg * 8;
                uint32_t dst = sb + bufoff + (uint32_t)(arr * BHALF + row * ROWB + seg * 16);
                CP_ASYNC16(dst, src);
            }
        }
    };
    prefetch(0, B0_OFF); CP_COMMIT();
    prefetch(1, B1_OFF); CP_COMMIT();

    // ---- stage A (128 tok x 256 c) as fp16 hi/lo, coalesced over tokens ---
    for (int it = 0; it < 128; it++) {
        int i  = it * 256 + tid;
        int tk = i & 127;
        int c  = i >> 7;
        float a = zb[(size_t)c * HW_DIM + tk];
        __half hi, lo;
        split16(a, hi, lo);
        *(__half*)(smem + AH_OFF + tk * ROWB + c * 2) = hi;
        *(__half*)(smem + AL_OFF + tk * ROWB + c * 2) = lo;
    }
    // all 1024 norms into smem
    #pragma unroll
    for (int it = 0; it < 4; it++) ns[it * 256 + tid] = g_norms[it * 256 + tid];

    // per-lane ldsm addresses
    const uint32_t aH = sb + AH_OFF + (uint32_t)((tg * 32 + l15) * ROWB + (lane >> 4) * 16);
    const uint32_t aL = aH + (uint32_t)(AL_OFF - AH_OFF);
    // B x4: matrices [nb0 k0-7][nb0 k8-15][nb1 k0-7][nb1 k8-15]
    const int bm  = lane >> 3;          // 0..3
    const int brw = cg * 16 + (bm >> 1) * 8 + (lane & 7);
    const uint32_t bAddr = (uint32_t)(brw * ROWB + (bm & 1) * 16);

    float bestv4[4];
    int   besti4[4];
    #pragma unroll
    for (int s = 0; s < 4; s++) { bestv4[s] = 3.4e38f; besti4[s] = 0; }

    for (int ch = 0; ch < CHUNKS; ch++) {
        const int k0c = ch * NCH;
        const uint32_t bufoff = (ch & 1) ? B1_OFF : B0_OFF;
        if (ch == CHUNKS - 1) CP_WAIT0(); else CP_WAIT1();
        __syncthreads();     // buf visible to all; also covers A staging at ch=0

        const uint32_t bH = sb + bufoff + bAddr;
        const uint32_t bL = bH + (uint32_t)BHALF;

        float hh[2][2][4], md[2][2][4];
        #pragma unroll
        for (int mt = 0; mt < 2; mt++)
            #pragma unroll
            for (int nb = 0; nb < 2; nb++)
                #pragma unroll
                for (int q = 0; q < 4; q++) { hh[mt][nb][q] = 0.f; md[mt][nb][q] = 0.f; }

        #pragma unroll 4
        for (int ks = 0; ks < KSTEPS; ks++) {
            uint32_t ah[2][4], al[2][4], bh4[4], bl4[4];
            ldsm4(bH + (uint32_t)(ks * 32), bh4);
            ldsm4(bL + (uint32_t)(ks * 32), bl4);
            #pragma unroll
            for (int mt = 0; mt < 2; mt++) {
                ldsm4(aH + (uint32_t)(mt * 16 * ROWB + ks * 32), ah[mt]);
                ldsm4(aL + (uint32_t)(mt * 16 * ROWB + ks * 32), al[mt]);
            }
            #pragma unroll
            for (int nb = 0; nb < 2; nb++) {
                uint32_t b0h = bh4[nb * 2], b1h = bh4[nb * 2 + 1];
                uint32_t b0l = bl4[nb * 2], b1l = bl4[nb * 2 + 1];
                #pragma unroll
                for (int mt = 0; mt < 2; mt++) {
                    mma_f16(hh[mt][nb], ah[mt], b0h, b1h);
                    mma_f16(md[mt][nb], ah[mt], b0l, b1l);
                    mma_f16(md[mt][nb], al[mt], b0h, b1h);
                }
            }
        }

        __syncthreads();     // all warps done reading buf
        if (ch + 2 < CHUNKS) { prefetch(ch + 2, bufoff); CP_COMMIT(); }

        // epilogue: dist = |e|^2 - 2 (hh + md/2048)
        #pragma unroll
        for (int nb = 0; nb < 2; nb++) {
            int cl = cg * 16 + nb * 8 + 2 * t;
            float nk0 = ns[k0c + cl];
            float nk1 = ns[k0c + cl + 1];
            int code0 = k0c + cl;
            #pragma unroll
            for (int mt = 0; mt < 2; mt++) {
                float d00 = nk0 - 2.f * (hh[mt][nb][0] + md[mt][nb][0] * LO_IS);
                float d01 = nk1 - 2.f * (hh[mt][nb][1] + md[mt][nb][1] * LO_IS);
                float d10 = nk0 - 2.f * (hh[mt][nb][2] + md[mt][nb][2] * LO_IS);
                float d11 = nk1 - 2.f * (hh[mt][nb][3] + md[mt][nb][3] * LO_IS);
                int s0 = mt * 2, s1 = mt * 2 + 1;
                if (d00 < bestv4[s0]) { bestv4[s0] = d00; besti4[s0] = code0; }
                if (d01 < bestv4[s0]) { bestv4[s0] = d01; besti4[s0] = code0 + 1; }
                if (d10 < bestv4[s1]) { bestv4[s1] = d10; besti4[s1] = code0; }
                if (d11 < bestv4[s1]) { bestv4[s1] = d11; besti4[s1] = code0 + 1; }
            }
        }
    }

    // lane-reduce across t (lanes 4g..4g+3 share a token row)
    #pragma unroll
    for (int s = 0; s < 4; s++) {
        #pragma unroll
        for (int m = 1; m <= 2; m <<= 1) {
            float v2 = __shfl_xor_sync(0xffffffffu, bestv4[s], m);
            int   i2 = __shfl_xor_sync(0xffffffffu, besti4[s], m);
            if (v2 < bestv4[s] || (v2 == bestv4[s] && i2 < besti4[s])) {
                bestv4[s] = v2; besti4[s] = i2;
            }
        }
    }
    if (t == 0) {
        #pragma unroll
        for (int s = 0; s < 4; s++) {
            int mt = s >> 1, h = s & 1;
            int tok = tg * 32 + mt * 16 + h * 8 + g;
            candv[tok * 2 + cg] = bestv4[s];
            candi[tok * 2 + cg] = besti4[s];
        }
    }
    __syncthreads();
    if (tid < MT) {
        float v0 = candv[tid * 2], v1 = candv[tid * 2 + 1];
        int   i0 = candi[tid * 2], i1 = candi[tid * 2 + 1];
        int bi;
        if (v1 < v0 || (v1 == v0 && i1 < i0)) bi = i1; else bi = i0;
        g_idx[n0 + tid] = bi;
        atomicAdd(&g_counts[bi], 1);
    }
}

// ---------------------------------------------------------------------------
// gather: 1024 blocks, 32 tokens/block, 8 threads per token (32 channels each)
__global__ __launch_bounds__(256)
void gather_loss_kernel(const float* __restrict__ z,
                        const float* __restrict__ cb,
                        float* __restrict__ out) {
    __shared__ float red[256];
    const int tid = threadIdx.x;
    const int tok = blockIdx.x * 32 + (tid & 31);
    const int cc  = tid >> 5;           // channel chunk 0..7 (32 channels)
    const int k   = g_idx[tok];
    const int b   = tok >> 10;
    const int hw  = tok & 1023;
    const float4* c4p = (const float4*)cb + (size_t)k * 64 + cc * 8;
    const size_t base = (size_t)b * (C_DIM * HW_DIM) + (size_t)cc * 32 * HW_DIM + hw;
    const float* zp = z + base;
    float* op = out + base;
    float s = 0.f;
    #pragma unroll
    for (int j = 0; j < 8; j++) {
        float4 e = c4p[j];
        int c = j * 4;
        float d0 = e.x - zp[(c + 0) * HW_DIM];
        float d1 = e.y - zp[(c + 1) * HW_DIM];
        float d2 = e.z - zp[(c + 2) * HW_DIM];
        float d3 = e.w - zp[(c + 3) * HW_DIM];
        s += d0 * d0 + d1 * d1 + d2 * d2 + d3 * d3;
        op[(c + 0) * HW_DIM] = e.x;
        op[(c + 1) * HW_DIM] = e.y;
        op[(c + 2) * HW_DIM] = e.z;
        op[(c + 3) * HW_DIM] = e.w;
    }
    red[tid] = s;
    __syncthreads();
    for (int off = 128; off > 0; off >>= 1) {
        if (tid < off) red[tid] += red[tid + off];
        __syncthreads();
    }
    if (tid == 0) g_partials[blockIdx.x] = red[0];
}

// ---------------------------------------------------------------------------
__global__ void finalize_kernel(float* __restrict__ out, int out_size) {
    __shared__ float s1[1024];
    __shared__ float s2[1024];
    const int tid = threadIdx.x;
    float ls = (tid < GL_BLOCKS) ? g_partials[tid] : 0.f;
    float p  = (float)g_counts[tid] * (1.0f / (float)N_TOK);
    float pc = fmaxf(p, 1e-10f);
    s1[tid] = ls;
    s2[tid] = pc * logf(pc);
    __syncthreads();
    for (int off = 512; off > 0; off >>= 1) {
        if (tid < off) { s1[tid] += s1[tid + off]; s2[tid] += s2[tid + off]; }
        __syncthreads();
    }
    if (tid == 0) {
        float mse = s1[0] * (1.0f / (float)Z_ELEMS);
        if (out_size >= Z_ELEMS + 1) out[Z_ELEMS]     = mse * (1.0f + BETA_F);
        if (out_size >= Z_ELEMS + 2) out[Z_ELEMS + 1] = expf(-s2[0]);
    }
}

// ---------------------------------------------------------------------------
extern "C" void kernel_launch(void* const* d_in, const int* in_sizes, int n_in,
                              void* d_out, int out_size) {
    const float* z  = (const float*)d_in[0];
    const float* cb = (const float*)d_in[1];
    float* out = (float*)d_out;

    cudaFuncSetAttribute(argmin_kernel,
                         cudaFuncAttributeMaxDynamicSharedMemorySize, SMEM_TOTAL);

    init_kernel<<<1, K_CODES>>>();
    split_cb_kernel<<<K_CODES, 256>>>(cb);
    norms_kernel<<<K_CODES / 8, 256>>>(cb);
    argmin_kernel<<<N_TOK / MT, 256, SMEM_TOTAL>>>(z, cb);
    gather_loss_kernel<<<GL_BLOCKS, 256>>>(z, cb, out);
    finalize_kernel<<<1, 1024>>>(out, out_size);
}